// round 12
// baseline (speedup 1.0000x reference)
#include <cuda_runtime.h>
#include <cuda_fp16.h>
#include <math.h>
#include <stdint.h>

#define BATCH 4
#define SEQ   2048
#define EMB   1024
#define NH    16
#define HD    64
#define MROWS (BATCH*SEQ)          // 8192
#define LDQKV (3*EMB)              // 3072

// ---- fp16 GEMM tiling: CTA 128x256, BK=64 halfs (128B rows) ----
#define BM 128
#define BN 256
#define BKH 64
#define GT 512
#define A_STAGE 16384              // bytes: 128 rows * 128B
#define B_STAGE 32768              // bytes: 256 rows * 128B
#define STAGE_BYTES (A_STAGE + B_STAGE)
#define NSTAGE 3
#define GEMM_SMEM_BYTES (NSTAGE*STAGE_BYTES)    // 147456

// ---- attention: padded rows of 72 halfs (144B -> bank shift 4/row) ----
#define RP 72
#define ATTN_SMEM_BYTES ((128*RP + 64*RP + 64*RP)*2)   // 36864

// Scratch as uint4 arrays (guarantees 16B alignment for cp.async)
__device__ uint4 g_qkv_raw[(size_t)MROWS * LDQKV / 8];
__device__ uint4 g_att_raw[(size_t)MROWS * EMB / 8];
__device__ uint4 g_xh_raw [(size_t)MROWS * EMB / 8];
__device__ uint4 g_wat_raw[(size_t)LDQKV * EMB / 8];   // transposed [3072][1024]
__device__ uint4 g_wpt_raw[(size_t)EMB * EMB / 8];     // transposed [1024][1024]

// ---------------------------------------------------------------------------
__device__ __forceinline__ void cp16(uint32_t dst, const void* src) {
    asm volatile("cp.async.cg.shared.global [%0], [%1], 16;\n" :: "r"(dst), "l"(src));
}
__device__ __forceinline__ void cp_commit() {
    asm volatile("cp.async.commit_group;\n" ::: "memory");
}
__device__ __forceinline__ void cp_wait1() {
    asm volatile("cp.async.wait_group 1;\n" ::: "memory");
}
__device__ __forceinline__ void cp_wait0() {
    asm volatile("cp.async.wait_group 0;\n" ::: "memory");
}
__device__ __forceinline__ uint32_t smem_u32(const void* p) {
    return (uint32_t)__cvta_generic_to_shared(p);
}
__device__ __forceinline__ void mma_f16(float* d, const uint32_t* a, const uint32_t* b) {
    asm volatile(
        "mma.sync.aligned.m16n8k16.row.col.f32.f16.f16.f32 "
        "{%0,%1,%2,%3}, {%4,%5,%6,%7}, {%8,%9}, {%0,%1,%2,%3};"
        : "+f"(d[0]), "+f"(d[1]), "+f"(d[2]), "+f"(d[3])
        : "r"(a[0]), "r"(a[1]), "r"(a[2]), "r"(a[3]), "r"(b[0]), "r"(b[1]));
}

// ---------------------------------------------------------------------------
// prepass: fp32 -> fp16
__global__ void to_half_kernel(const float* __restrict__ src, __half* __restrict__ dst, int n2)
{
    int i = blockIdx.x * blockDim.x + threadIdx.x;
    if (i < n2) {
        float2 f = ((const float2*)src)[i];
        ((__half2*)dst)[i] = __floats2half2_rn(f.x, f.y);
    }
}

// prepass: transpose + convert. dst[c][r] = half(src[r][c]); R,C % 32 == 0
__global__ void transpose_half_kernel(const float* __restrict__ src, __half* __restrict__ dst,
                                      int R, int C)
{
    __shared__ float t[32][33];
    int bx = blockIdx.x * 32, by = blockIdx.y * 32;
    int x = threadIdx.x, y = threadIdx.y;   // 32 x 8
    #pragma unroll
    for (int j = 0; j < 4; j++)
        t[y + 8*j][x] = src[(size_t)(by + y + 8*j) * C + bx + x];
    __syncthreads();
    #pragma unroll
    for (int j = 0; j < 4; j++)
        dst[(size_t)(bx + y + 8*j) * R + by + x] = __float2half_rn(t[x][y + 8*j]);
}

// ---------------------------------------------------------------------------
// fp16 tensor-core GEMM: C[M,N] = A[M,K] @ Bt[N,K]^T + bias[N]
// A,Bt half (Bt = W transposed, K contiguous). 128x256xBK64, 16 warps,
// warp tile 32x64, mma m16n8k16, 3-stage cp.async, one barrier per tile.
// Both smem tiles: rows of 128B with chunk-XOR swizzle (chunk ^= row&7).
// ---------------------------------------------------------------------------
__global__ __launch_bounds__(GT, 1)
void gemm_f16(const __half* __restrict__ A, const __half* __restrict__ Bt,
              const float* __restrict__ bias, void* __restrict__ Cout,
              int Ndim, int Kdim, int out_half)
{
    extern __shared__ char smg[];

    const int tid  = threadIdx.x;
    const int m0   = blockIdx.y * BM;
    const int n0   = blockIdx.x * BN;

    const int lane = tid & 31;
    const int tig  = lane & 3;
    const int grp  = lane >> 2;
    const int wid  = tid >> 5;
    const int mw   = (wid >> 2) * 32;
    const int nw   = (wid & 3) * 64;

    // global-load decomposition: chunks of 16B (8 halfs)
    const int ch  = tid & 7;          // chunk in 128B row
    const int rb  = tid >> 3;         // 0..63

    // A: rows rb, rb+64 (2 chunks/thread); B: rows rb + 64j (4 chunks/thread)
    uint32_t aoff[2], boff[4];
    const __half* agp[2];
    const __half* bgp[4];
    #pragma unroll
    for (int i = 0; i < 2; i++) {
        int r = rb + 64 * i;
        aoff[i] = r * 128 + ((ch ^ (r & 7)) << 4);
        agp[i]  = A + (size_t)(m0 + r) * Kdim + ch * 8;
    }
    #pragma unroll
    for (int i = 0; i < 4; i++) {
        int r = rb + 64 * i;
        boff[i] = r * 128 + ((ch ^ (r & 7)) << 4);
        bgp[i]  = Bt + (size_t)(n0 + r) * Kdim + ch * 8;
    }
    const uint32_t sb = smem_u32(smg);

    float acc[2][8][4];
    #pragma unroll
    for (int mi = 0; mi < 2; mi++)
        #pragma unroll
        for (int ni = 0; ni < 8; ni++)
            #pragma unroll
            for (int c = 0; c < 4; c++) acc[mi][ni][c] = 0.f;

    const int NT = Kdim / BKH;

    // prologue: tiles 0,1
    #pragma unroll
    for (int p = 0; p < 2; p++) {
        uint32_t so = sb + p * STAGE_BYTES;
        int koff = p * BKH;
        #pragma unroll
        for (int i = 0; i < 2; i++)
            cp16(so + aoff[i], agp[i] + koff);
        #pragma unroll
        for (int i = 0; i < 4; i++)
            cp16(so + A_STAGE + boff[i], bgp[i] + koff);
        cp_commit();
    }

    for (int t = 0; t < NT; t++) {
        cp_wait1();
        __syncthreads();
        if (t + 2 < NT) {
            uint32_t so = sb + ((t + 2) % NSTAGE) * STAGE_BYTES;
            int koff = (t + 2) * BKH;
            #pragma unroll
            for (int i = 0; i < 2; i++)
                cp16(so + aoff[i], agp[i] + koff);
            #pragma unroll
            for (int i = 0; i < 4; i++)
                cp16(so + A_STAGE + boff[i], bgp[i] + koff);
        }
        cp_commit();

        const char* cA = smg + (t % NSTAGE) * STAGE_BYTES;
        const char* cB = cA + A_STAGE;

        #pragma unroll
        for (int s = 0; s < 4; s++) {           // 4 k16 steps per 64-half tile
            const int c0 = 2 * s, c1 = 2 * s + 1;
            uint32_t afr[2][4];
            #pragma unroll
            for (int mi = 0; mi < 2; mi++) {
                int m1 = mw + 16 * mi + grp;
                int m2 = m1 + 8;
                afr[mi][0] = *(const uint32_t*)(cA + m1 * 128 + ((c0 ^ (m1 & 7)) << 4) + 4 * tig);
                afr[mi][1] = *(const uint32_t*)(cA + m2 * 128 + ((c0 ^ (m2 & 7)) << 4) + 4 * tig);
                afr[mi][2] = *(const uint32_t*)(cA + m1 * 128 + ((c1 ^ (m1 & 7)) << 4) + 4 * tig);
                afr[mi][3] = *(const uint32_t*)(cA + m2 * 128 + ((c1 ^ (m2 & 7)) << 4) + 4 * tig);
            }
            uint32_t bfr[8][2];
            #pragma unroll
            for (int ni = 0; ni < 8; ni++) {
                int n = nw + 8 * ni + grp;
                bfr[ni][0] = *(const uint32_t*)(cB + n * 128 + ((c0 ^ (n & 7)) << 4) + 4 * tig);
                bfr[ni][1] = *(const uint32_t*)(cB + n * 128 + ((c1 ^ (n & 7)) << 4) + 4 * tig);
            }
            #pragma unroll
            for (int mi = 0; mi < 2; mi++)
                #pragma unroll
                for (int ni = 0; ni < 8; ni++)
                    mma_f16(acc[mi][ni], afr[mi], bfr[ni]);
        }
    }

    float bl0[8], bl1[8];
    #pragma unroll
    for (int ni = 0; ni < 8; ni++) {
        int col = n0 + nw + 8 * ni + 2 * tig;
        bl0[ni] = bias[col];
        bl1[ni] = bias[col + 1];
    }
    if (out_half) {
        __half* C = (__half*)Cout;
        #pragma unroll
        for (int mi = 0; mi < 2; mi++) {
            int row = m0 + mw + 16 * mi + grp;
            #pragma unroll
            for (int ni = 0; ni < 8; ni++) {
                int col = n0 + nw + 8 * ni + 2 * tig;
                *(__half2*)&C[(size_t)row * Ndim + col] =
                    __floats2half2_rn(acc[mi][ni][0] + bl0[ni], acc[mi][ni][1] + bl1[ni]);
                *(__half2*)&C[(size_t)(row + 8) * Ndim + col] =
                    __floats2half2_rn(acc[mi][ni][2] + bl0[ni], acc[mi][ni][3] + bl1[ni]);
            }
        }
    } else {
        float* C = (float*)Cout;
        #pragma unroll
        for (int mi = 0; mi < 2; mi++) {
            int row = m0 + mw + 16 * mi + grp;
            #pragma unroll
            for (int ni = 0; ni < 8; ni++) {
                int col = n0 + nw + 8 * ni + 2 * tig;
                float2 v0 = { acc[mi][ni][0] + bl0[ni], acc[mi][ni][1] + bl1[ni] };
                float2 v1 = { acc[mi][ni][2] + bl0[ni], acc[mi][ni][3] + bl1[ni] };
                *(float2*)&C[(size_t)row * Ndim + col] = v0;
                *(float2*)&C[(size_t)(row + 8) * Ndim + col] = v1;
            }
        }
    }
}

// ---------------------------------------------------------------------------
// fp16 flash attention (mma m16n8k16, fp32 softmax), causal.
// Rows padded to 72 halfs (144B) -> per-row bank shift of 4 -> all fragment
// LDS conflict-free. V transposed in-kernel (Vt[d][key]) for the PV B-frag.
// P aliases Q (Q frags hoisted to registers). 36 KB smem.
// ---------------------------------------------------------------------------
__global__ __launch_bounds__(256, 2)
void attn_f16(const __half* __restrict__ qkv, __half* __restrict__ att)
{
    extern __shared__ __half sh[];
    __half* Qs = sh;                 // 128 x RP (aliased as Ps)
    __half* Ps = sh;
    __half* Ks = sh + 128 * RP;      // 64 x RP   [key][d]
    __half* Vt = Ks + 64 * RP;       // 64 x RP   [d][key]

    const int tid  = threadIdx.x;
    const int lane = tid & 31;
    const int w    = tid >> 5;
    const int tig  = lane & 3;
    const int grp  = lane >> 2;
    const int qt = blockIdx.x, h = blockIdx.y, b = blockIdx.z;
    const int q0 = qt * 128;
    const size_t rowbase = (size_t)b * SEQ;
    const int colq = h * HD, colk = EMB + h * HD, colv = 2 * EMB + h * HD;

    const char* Qb = (const char*)Qs;
    const char* Pb = (const char*)Ps;
    const char* Kb = (const char*)Ks;
    const char* Vb = (const char*)Vt;

    // load Q tile (128 rows x 128B) via cp.async into padded rows
    {
        #pragma unroll
        for (int t = 0; t < 4; t++) {
            int idx = tid + t * 256;
            int r = idx >> 3, c = idx & 7;
            cp16(smem_u32(Qb + r * 144 + c * 16),
                 qkv + (rowbase + q0 + r) * LDQKV + colq + c * 8);
        }
        cp_commit();
        cp_wait0();
        __syncthreads();
    }

    // hoist Q fragments (4 k16 steps)
    uint32_t qa[4][4];
    {
        int m1 = w * 16 + grp, m2 = m1 + 8;
        #pragma unroll
        for (int s = 0; s < 4; s++) {
            qa[s][0] = *(const uint32_t*)(Qb + m1 * 144 + 32 * s + 4 * tig);
            qa[s][1] = *(const uint32_t*)(Qb + m2 * 144 + 32 * s + 4 * tig);
            qa[s][2] = *(const uint32_t*)(Qb + m1 * 144 + 32 * s + 16 + 4 * tig);
            qa[s][3] = *(const uint32_t*)(Qb + m2 * 144 + 32 * s + 16 + 4 * tig);
        }
    }

    // per-thread K chunk slots (2 per thread)
    uint32_t kdst[2];
    const __half* ksrc[2];
    #pragma unroll
    for (int t = 0; t < 2; t++) {
        int idx = tid + t * 256;
        int r = idx >> 3, c = idx & 7;
        kdst[t] = smem_u32(Kb + r * 144 + c * 16);
        ksrc[t] = qkv + (rowbase + r) * LDQKV + colk + c * 8;
    }
    // V transpose mapping: 4 iters, d0 = 2*(tid>>5) + 16j, key0 = (tid&31)*2
    const int vd0base = 2 * (tid >> 5);
    const int vkey0   = (lane) * 2;

    float o[8][4];
    #pragma unroll
    for (int ni = 0; ni < 8; ni++)
        #pragma unroll
        for (int c = 0; c < 4; c++) o[ni][c] = 0.f;
    float m0 = -1e30f, m1 = -1e30f, l0 = 0.f, l1 = 0.f;

    const int r0g = q0 + w * 16 + grp;
    const int r1g = r0g + 8;

    const int nkt = 2 * qt + 2;
    for (int kt = 0; kt < nkt; kt++) {
        const int k0 = kt * 64;
        __syncthreads();   // prior tile's K/Vt/P consumers done
        // K via cp.async
        #pragma unroll
        for (int t = 0; t < 2; t++)
            cp16(kdst[t], ksrc[t] + (size_t)k0 * LDQKV);
        cp_commit();
        // V transposed, scalar half2 path
        #pragma unroll
        for (int j = 0; j < 4; j++) {
            int d0 = vd0base + 16 * j;
            const __half* v0p = qkv + (rowbase + k0 + vkey0) * LDQKV + colv + d0;
            __half2 p0 = *(const __half2*)v0p;            // v[key0][d0], v[key0][d0+1]
            __half2 p1 = *(const __half2*)(v0p + LDQKV);  // v[key0+1][d0], ...
            *(__half2*)(Vb + d0 * 144 + vkey0 * 2) =
                __halves2half2(__low2half(p0), __low2half(p1));
            *(__half2*)(Vb + (d0 + 1) * 144 + vkey0 * 2) =
                __halves2half2(__high2half(p0), __high2half(p1));
        }
        cp_wait0();
        __syncthreads();

        // S = Q K^T  (K rows [key][d]; B-frag reads d-contiguous)
        float s[8][4];
        #pragma unroll
        for (int ni = 0; ni < 8; ni++)
            #pragma unroll
            for (int c = 0; c < 4; c++) s[ni][c] = 0.f;
        #pragma unroll
        for (int ks = 0; ks < 4; ks++) {
            #pragma unroll
            for (int ni = 0; ni < 8; ni++) {
                int n = 8 * ni + grp;
                uint32_t bfr[2];
                bfr[0] = *(const uint32_t*)(Kb + n * 144 + 32 * ks + 4 * tig);
                bfr[1] = *(const uint32_t*)(Kb + n * 144 + 32 * ks + 16 + 4 * tig);
                mma_f16(s[ni], qa[ks], bfr);
            }
        }
        #pragma unroll
        for (int ni = 0; ni < 8; ni++)
            #pragma unroll
            for (int c = 0; c < 4; c++) s[ni][c] *= 0.125f;

        if (k0 + 63 > r0g) {
            #pragma unroll
            for (int ni = 0; ni < 8; ni++) {
                int c0 = k0 + ni * 8 + 2 * tig;
                if (c0     > r0g) s[ni][0] = -1e30f;
                if (c0 + 1 > r0g) s[ni][1] = -1e30f;
                if (c0     > r1g) s[ni][2] = -1e30f;
                if (c0 + 1 > r1g) s[ni][3] = -1e30f;
            }
        }

        float pm0 = -1e30f, pm1 = -1e30f;
        #pragma unroll
        for (int ni = 0; ni < 8; ni++) {
            pm0 = fmaxf(pm0, fmaxf(s[ni][0], s[ni][1]));
            pm1 = fmaxf(pm1, fmaxf(s[ni][2], s[ni][3]));
        }
        pm0 = fmaxf(pm0, __shfl_xor_sync(0xffffffffu, pm0, 1));
        pm0 = fmaxf(pm0, __shfl_xor_sync(0xffffffffu, pm0, 2));
        pm1 = fmaxf(pm1, __shfl_xor_sync(0xffffffffu, pm1, 1));
        pm1 = fmaxf(pm1, __shfl_xor_sync(0xffffffffu, pm1, 2));
        float mn0 = fmaxf(m0, pm0), mn1 = fmaxf(m1, pm1);
        float a0 = __expf(m0 - mn0), a1 = __expf(m1 - mn1);
        m0 = mn0; m1 = mn1;

        float rs0 = 0.f, rs1 = 0.f;
        {
            char* p0p = (char*)Pb + (w * 16 + grp) * 144 + 4 * tig;
            char* p1p = p0p + 8 * 144;
            #pragma unroll
            for (int ni = 0; ni < 8; ni++) {
                float e0 = __expf(s[ni][0] - mn0);
                float e1 = __expf(s[ni][1] - mn0);
                float e2 = __expf(s[ni][2] - mn1);
                float e3 = __expf(s[ni][3] - mn1);
                rs0 += e0 + e1; rs1 += e2 + e3;
                *(__half2*)(p0p + ni * 16) = __floats2half2_rn(e0, e1);
                *(__half2*)(p1p + ni * 16) = __floats2half2_rn(e2, e3);
            }
        }
        rs0 += __shfl_xor_sync(0xffffffffu, rs0, 1);
        rs0 += __shfl_xor_sync(0xffffffffu, rs0, 2);
        rs1 += __shfl_xor_sync(0xffffffffu, rs1, 1);
        rs1 += __shfl_xor_sync(0xffffffffu, rs1, 2);
        l0 = l0 * a0 + rs0;
        l1 = l1 * a1 + rs1;

        #pragma unroll
        for (int ni = 0; ni < 8; ni++) {
            o[ni][0] *= a0; o[ni][1] *= a0;
            o[ni][2] *= a1; o[ni][3] *= a1;
        }
        __syncwarp();

        // O += P @ V  (A-frag from Ps rows, B-frag from Vt rows)
        {
            int m1r = w * 16 + grp, m2r = m1r + 8;
            #pragma unroll
            for (int ks = 0; ks < 4; ks++) {
                uint32_t pa[4];
                pa[0] = *(const uint32_t*)(Pb + m1r * 144 + 32 * ks + 4 * tig);
                pa[1] = *(const uint32_t*)(Pb + m2r * 144 + 32 * ks + 4 * tig);
                pa[2] = *(const uint32_t*)(Pb + m1r * 144 + 32 * ks + 16 + 4 * tig);
                pa[3] = *(const uint32_t*)(Pb + m2r * 144 + 32 * ks + 16 + 4 * tig);
                #pragma unroll
                for (int ni = 0; ni < 8; ni++) {
                    int d = 8 * ni + grp;
                    uint32_t bfr[2];
                    bfr[0] = *(const uint32_t*)(Vb + d * 144 + 32 * ks + 4 * tig);
                    bfr[1] = *(const uint32_t*)(Vb + d * 144 + 32 * ks + 16 + 4 * tig);
                    mma_f16(o[ni], pa, bfr);
                }
            }
        }
    }

    float inv0 = 1.f / l0, inv1 = 1.f / l1;
    #pragma unroll
    for (int ni = 0; ni < 8; ni++) {
        int col = h * HD + ni * 8 + 2 * tig;
        *(__half2*)&att[(rowbase + r0g) * EMB + col] =
            __floats2half2_rn(o[ni][0] * inv0, o[ni][1] * inv0);
        *(__half2*)&att[(rowbase + r1g) * EMB + col] =
            __floats2half2_rn(o[ni][2] * inv1, o[ni][3] * inv1);
    }
}

// ---------------------------------------------------------------------------
extern "C" void kernel_launch(void* const* d_in, const int* in_sizes, int n_in,
                              void* d_out, int out_size)
{
    const float* x      = (const float*)d_in[0];
    const float* w_attn = (const float*)d_in[1];
    const float* b_attn = (const float*)d_in[2];
    const float* w_proj = (const float*)d_in[3];
    const float* b_proj = (const float*)d_in[4];
    float* out = (float*)d_out;

    void *qkvp, *attp, *xhp, *watp, *wptp;
    cudaGetSymbolAddress(&qkvp, g_qkv_raw);
    cudaGetSymbolAddress(&attp, g_att_raw);
    cudaGetSymbolAddress(&xhp,  g_xh_raw);
    cudaGetSymbolAddress(&watp, g_wat_raw);
    cudaGetSymbolAddress(&wptp, g_wpt_raw);
    __half* qkv = (__half*)qkvp;
    __half* att = (__half*)attp;
    __half* xh  = (__half*)xhp;
    __half* wat = (__half*)watp;
    __half* wpt = (__half*)wptp;

    cudaFuncSetAttribute(gemm_f16, cudaFuncAttributeMaxDynamicSharedMemorySize, GEMM_SMEM_BYTES);
    cudaFuncSetAttribute(attn_f16, cudaFuncAttributeMaxDynamicSharedMemorySize, ATTN_SMEM_BYTES);

    // 0) prepass: x -> half; weights -> half + transpose ([N][K])
    to_half_kernel<<<(MROWS * EMB / 2 + 255) / 256, 256>>>(x, xh, MROWS * EMB / 2);
    {
        dim3 blk(32, 8);
        dim3 g1(LDQKV / 32, EMB / 32);
        transpose_half_kernel<<<g1, blk>>>(w_attn, wat, EMB, LDQKV);
        dim3 g2(EMB / 32, EMB / 32);
        transpose_half_kernel<<<g2, blk>>>(w_proj, wpt, EMB, EMB);
    }

    // 1) qkv(half) = x @ w_attn + b_attn
    {
        dim3 grid(LDQKV / BN, MROWS / BM);
        gemm_f16<<<grid, GT, GEMM_SMEM_BYTES>>>(xh, wat, b_attn, qkv, LDQKV, EMB, 1);
    }
    // 2) fp16 flash attention -> att(half)
    {
        dim3 grid(SEQ / 128, NH, BATCH);
        attn_f16<<<grid, 256, ATTN_SMEM_BYTES>>>(qkv, att);
    }
    // 3) out(fp32) = att @ w_proj + b_proj
    {
        dim3 grid(EMB / BN, MROWS / BM);
        gemm_f16<<<grid, GT, GEMM_SMEM_BYTES>>>(att, wpt, b_proj, out, EMB, EMB, 0);
    }
}

// round 15
// speedup vs baseline: 1.8355x; 1.8355x over previous
#include <cuda_runtime.h>
#include <cuda_fp16.h>
#include <math.h>
#include <stdint.h>

#define BATCH 4
#define SEQ   2048
#define EMB   1024
#define NH    16
#define HD    64
#define MROWS (BATCH*SEQ)          // 8192
#define LDQKV (3*EMB)              // 3072

// ---- fp16 GEMM tiling: CTA 128x256, BK=64 halfs (128B rows) ----
#define BM 128
#define BN 256
#define BKH 64
#define GT 512
#define A_STAGE 16384              // bytes: 128 rows * 128B
#define B_STAGE 32768              // bytes: 256 rows * 128B
#define STAGE_BYTES (A_STAGE + B_STAGE)
#define NSTAGE 3
#define GEMM_SMEM_BYTES (NSTAGE*STAGE_BYTES)    // 147456

// ---- attention: rows padded to 72 halfs (144B); K/Vt double buffered ----
#define RP 72
#define Q_SLAB   (128*RP*2)                     // 18432 B (aliased as P)
#define KV_SLAB  (64*RP*2)                      // 9216 B per buffer
#define ATTN_SMEM_BYTES (Q_SLAB + 4*KV_SLAB)    // 55296 B

// Scratch as uint4 arrays (guarantees 16B alignment for cp.async)
__device__ uint4 g_qkv_raw[(size_t)MROWS * LDQKV / 8];
__device__ uint4 g_att_raw[(size_t)MROWS * EMB / 8];
__device__ uint4 g_xh_raw [(size_t)MROWS * EMB / 8];
__device__ uint4 g_wat_raw[(size_t)LDQKV * EMB / 8];   // transposed [3072][1024]
__device__ uint4 g_wpt_raw[(size_t)EMB * EMB / 8];     // transposed [1024][1024]
__device__ uint4 g_vt_raw [(size_t)BATCH * NH * HD * SEQ / 8];  // V^T [b][h][d][T]

// ---------------------------------------------------------------------------
__device__ __forceinline__ void cp16(uint32_t dst, const void* src) {
    asm volatile("cp.async.cg.shared.global [%0], [%1], 16;\n" :: "r"(dst), "l"(src));
}
__device__ __forceinline__ void cp_commit() {
    asm volatile("cp.async.commit_group;\n" ::: "memory");
}
__device__ __forceinline__ void cp_wait1() {
    asm volatile("cp.async.wait_group 1;\n" ::: "memory");
}
__device__ __forceinline__ void cp_wait0() {
    asm volatile("cp.async.wait_group 0;\n" ::: "memory");
}
__device__ __forceinline__ uint32_t smem_u32(const void* p) {
    return (uint32_t)__cvta_generic_to_shared(p);
}
__device__ __forceinline__ void mma_f16(float* d, const uint32_t* a, const uint32_t* b) {
    asm volatile(
        "mma.sync.aligned.m16n8k16.row.col.f32.f16.f16.f32 "
        "{%0,%1,%2,%3}, {%4,%5,%6,%7}, {%8,%9}, {%0,%1,%2,%3};"
        : "+f"(d[0]), "+f"(d[1]), "+f"(d[2]), "+f"(d[3])
        : "r"(a[0]), "r"(a[1]), "r"(a[2]), "r"(a[3]), "r"(b[0]), "r"(b[1]));
}

// ---------------------------------------------------------------------------
// prepass: fp32 -> fp16
__global__ void to_half_kernel(const float* __restrict__ src, __half* __restrict__ dst, int n2)
{
    int i = blockIdx.x * blockDim.x + threadIdx.x;
    if (i < n2) {
        float2 f = ((const float2*)src)[i];
        ((__half2*)dst)[i] = __floats2half2_rn(f.x, f.y);
    }
}

// prepass: transpose + convert. dst[c][r] = half(src[r][c]); R,C % 32 == 0
__global__ void transpose_half_kernel(const float* __restrict__ src, __half* __restrict__ dst,
                                      int R, int C)
{
    __shared__ float t[32][33];
    int bx = blockIdx.x * 32, by = blockIdx.y * 32;
    int x = threadIdx.x, y = threadIdx.y;   // 32 x 8
    #pragma unroll
    for (int j = 0; j < 4; j++)
        t[y + 8*j][x] = src[(size_t)(by + y + 8*j) * C + bx + x];
    __syncthreads();
    #pragma unroll
    for (int j = 0; j < 4; j++)
        dst[(size_t)(bx + y + 8*j) * R + by + x] = __float2half_rn(t[x][y + 8*j]);
}

// prepass: transpose V out of qkv. vt[((b*NH+h)*HD + d)*SEQ + key] = qkv[...V...]
// grid (SEQ/64, NH, BATCH), 256 threads; 64x64 half tile per block.
__global__ void transpose_v_kernel(const __half* __restrict__ qkv, __half* __restrict__ vt)
{
    __shared__ __half tile[64][72];
    const int kt = blockIdx.x, h = blockIdx.y, b = blockIdx.z;
    const int k0 = kt * 64;
    const int tid = threadIdx.x;
    const __half* src = qkv + ((size_t)b * SEQ + k0) * LDQKV + 2 * EMB + h * HD;
    #pragma unroll
    for (int t = 0; t < 2; t++) {
        int idx = tid + t * 256;
        int r = idx >> 3, c = idx & 7;
        *(uint4*)&tile[r][c * 8] = *(const uint4*)(src + (size_t)r * LDQKV + c * 8);
    }
    __syncthreads();
    __half* dst = vt + ((size_t)(b * NH + h) * HD) * SEQ + k0;
    const int d  = tid >> 2;
    const int kb = (tid & 3) * 16;
    #pragma unroll
    for (int i = 0; i < 8; i++) {
        int key = kb + 2 * i;
        *(__half2*)(dst + (size_t)d * SEQ + key) =
            __halves2half2(tile[key][d], tile[key + 1][d]);
    }
}

// ---------------------------------------------------------------------------
// fp16 tensor-core GEMM: C[M,N] = A[M,K] @ Bt[N,K]^T + bias[N]  (unchanged R12)
// ---------------------------------------------------------------------------
__global__ __launch_bounds__(GT, 1)
void gemm_f16(const __half* __restrict__ A, const __half* __restrict__ Bt,
              const float* __restrict__ bias, void* __restrict__ Cout,
              int Ndim, int Kdim, int out_half)
{
    extern __shared__ char smg[];

    const int tid  = threadIdx.x;
    const int m0   = blockIdx.y * BM;
    const int n0   = blockIdx.x * BN;

    const int lane = tid & 31;
    const int tig  = lane & 3;
    const int grp  = lane >> 2;
    const int wid  = tid >> 5;
    const int mw   = (wid >> 2) * 32;
    const int nw   = (wid & 3) * 64;

    const int ch  = tid & 7;
    const int rb  = tid >> 3;

    uint32_t aoff[2], boff[4];
    const __half* agp[2];
    const __half* bgp[4];
    #pragma unroll
    for (int i = 0; i < 2; i++) {
        int r = rb + 64 * i;
        aoff[i] = r * 128 + ((ch ^ (r & 7)) << 4);
        agp[i]  = A + (size_t)(m0 + r) * Kdim + ch * 8;
    }
    #pragma unroll
    for (int i = 0; i < 4; i++) {
        int r = rb + 64 * i;
        boff[i] = r * 128 + ((ch ^ (r & 7)) << 4);
        bgp[i]  = Bt + (size_t)(n0 + r) * Kdim + ch * 8;
    }
    const uint32_t sb = smem_u32(smg);

    float acc[2][8][4];
    #pragma unroll
    for (int mi = 0; mi < 2; mi++)
        #pragma unroll
        for (int ni = 0; ni < 8; ni++)
            #pragma unroll
            for (int c = 0; c < 4; c++) acc[mi][ni][c] = 0.f;

    const int NT = Kdim / BKH;

    #pragma unroll
    for (int p = 0; p < 2; p++) {
        uint32_t so = sb + p * STAGE_BYTES;
        int koff = p * BKH;
        #pragma unroll
        for (int i = 0; i < 2; i++)
            cp16(so + aoff[i], agp[i] + koff);
        #pragma unroll
        for (int i = 0; i < 4; i++)
            cp16(so + A_STAGE + boff[i], bgp[i] + koff);
        cp_commit();
    }

    for (int t = 0; t < NT; t++) {
        cp_wait1();
        __syncthreads();
        if (t + 2 < NT) {
            uint32_t so = sb + ((t + 2) % NSTAGE) * STAGE_BYTES;
            int koff = (t + 2) * BKH;
            #pragma unroll
            for (int i = 0; i < 2; i++)
                cp16(so + aoff[i], agp[i] + koff);
            #pragma unroll
            for (int i = 0; i < 4; i++)
                cp16(so + A_STAGE + boff[i], bgp[i] + koff);
        }
        cp_commit();

        const char* cA = smg + (t % NSTAGE) * STAGE_BYTES;
        const char* cB = cA + A_STAGE;

        #pragma unroll
        for (int s = 0; s < 4; s++) {
            const int c0 = 2 * s, c1 = 2 * s + 1;
            uint32_t afr[2][4];
            #pragma unroll
            for (int mi = 0; mi < 2; mi++) {
                int m1 = mw + 16 * mi + grp;
                int m2 = m1 + 8;
                afr[mi][0] = *(const uint32_t*)(cA + m1 * 128 + ((c0 ^ (m1 & 7)) << 4) + 4 * tig);
                afr[mi][1] = *(const uint32_t*)(cA + m2 * 128 + ((c0 ^ (m2 & 7)) << 4) + 4 * tig);
                afr[mi][2] = *(const uint32_t*)(cA + m1 * 128 + ((c1 ^ (m1 & 7)) << 4) + 4 * tig);
                afr[mi][3] = *(const uint32_t*)(cA + m2 * 128 + ((c1 ^ (m2 & 7)) << 4) + 4 * tig);
            }
            uint32_t bfr[8][2];
            #pragma unroll
            for (int ni = 0; ni < 8; ni++) {
                int n = nw + 8 * ni + grp;
                bfr[ni][0] = *(const uint32_t*)(cB + n * 128 + ((c0 ^ (n & 7)) << 4) + 4 * tig);
                bfr[ni][1] = *(const uint32_t*)(cB + n * 128 + ((c1 ^ (n & 7)) << 4) + 4 * tig);
            }
            #pragma unroll
            for (int mi = 0; mi < 2; mi++)
                #pragma unroll
                for (int ni = 0; ni < 8; ni++)
                    mma_f16(acc[mi][ni], afr[mi], bfr[ni]);
        }
    }

    float bl0[8], bl1[8];
    #pragma unroll
    for (int ni = 0; ni < 8; ni++) {
        int col = n0 + nw + 8 * ni + 2 * tig;
        bl0[ni] = bias[col];
        bl1[ni] = bias[col + 1];
    }
    if (out_half) {
        __half* C = (__half*)Cout;
        #pragma unroll
        for (int mi = 0; mi < 2; mi++) {
            int row = m0 + mw + 16 * mi + grp;
            #pragma unroll
            for (int ni = 0; ni < 8; ni++) {
                int col = n0 + nw + 8 * ni + 2 * tig;
                *(__half2*)&C[(size_t)row * Ndim + col] =
                    __floats2half2_rn(acc[mi][ni][0] + bl0[ni], acc[mi][ni][1] + bl1[ni]);
                *(__half2*)&C[(size_t)(row + 8) * Ndim + col] =
                    __floats2half2_rn(acc[mi][ni][2] + bl0[ni], acc[mi][ni][3] + bl1[ni]);
            }
        }
    } else {
        float* C = (float*)Cout;
        #pragma unroll
        for (int mi = 0; mi < 2; mi++) {
            int row = m0 + mw + 16 * mi + grp;
            #pragma unroll
            for (int ni = 0; ni < 8; ni++) {
                int col = n0 + nw + 8 * ni + 2 * tig;
                float2 v0 = { acc[mi][ni][0] + bl0[ni], acc[mi][ni][1] + bl1[ni] };
                float2 v1 = { acc[mi][ni][2] + bl0[ni], acc[mi][ni][3] + bl1[ni] };
                *(float2*)&C[(size_t)row * Ndim + col] = v0;
                *(float2*)&C[(size_t)(row + 8) * Ndim + col] = v1;
            }
        }
    }
}

// ---------------------------------------------------------------------------
// fp16 flash attention, causal. K and pre-transposed Vt tiles double-buffered
// via cp.async (prefetch kt+1 during compute of kt). P aliases Q. 54 KB smem.
// ---------------------------------------------------------------------------
__global__ __launch_bounds__(256, 2)
void attn_f16(const __half* __restrict__ qkv, const __half* __restrict__ vt,
              __half* __restrict__ att)
{
    extern __shared__ char shb[];
    char* Qb = shb;                       // 128 x 144B (aliased as P)
    char* Pb = shb;
    char* Kbuf[2]  = { shb + Q_SLAB,              shb + Q_SLAB + KV_SLAB };
    char* Vbuf[2]  = { shb + Q_SLAB + 2*KV_SLAB,  shb + Q_SLAB + 3*KV_SLAB };

    const int tid  = threadIdx.x;
    const int lane = tid & 31;
    const int w    = tid >> 5;
    const int tig  = lane & 3;
    const int grp  = lane >> 2;
    const int qt = blockIdx.x, h = blockIdx.y, b = blockIdx.z;
    const int q0 = qt * 128;
    const size_t rowbase = (size_t)b * SEQ;
    const int colq = h * HD, colk = EMB + h * HD;

    // per-thread K/Vt chunk mappings (2 chunks each)
    uint32_t kdst[2][2], vdst[2][2];
    const __half* ksrc[2];
    const __half* vsrc[2];
    #pragma unroll
    for (int t = 0; t < 2; t++) {
        int idx = tid + t * 256;
        int r = idx >> 3, c = idx & 7;
        #pragma unroll
        for (int bf = 0; bf < 2; bf++) {
            kdst[bf][t] = smem_u32(Kbuf[bf] + r * 144 + c * 16);
            vdst[bf][t] = smem_u32(Vbuf[bf] + r * 144 + c * 16);
        }
        ksrc[t] = qkv + (rowbase + r) * LDQKV + colk + c * 8;
        vsrc[t] = vt + ((size_t)(b * NH + h) * HD + r) * SEQ + c * 8;
    }

    // prologue: Q tile + K/Vt tile 0
    {
        #pragma unroll
        for (int t = 0; t < 4; t++) {
            int idx = tid + t * 256;
            int r = idx >> 3, c = idx & 7;
            cp16(smem_u32(Qb + r * 144 + c * 16),
                 qkv + (rowbase + q0 + r) * LDQKV + colq + c * 8);
        }
        #pragma unroll
        for (int t = 0; t < 2; t++) {
            cp16(kdst[0][t], ksrc[t]);
            cp16(vdst[0][t], vsrc[t]);
        }
        cp_commit();
        cp_wait0();
        __syncthreads();
    }

    // hoist Q fragments (4 k16 steps); each warp reads only its own 16 rows
    uint32_t qa[4][4];
    {
        int m1 = w * 16 + grp, m2 = m1 + 8;
        #pragma unroll
        for (int s = 0; s < 4; s++) {
            qa[s][0] = *(const uint32_t*)(Qb + m1 * 144 + 32 * s + 4 * tig);
            qa[s][1] = *(const uint32_t*)(Qb + m2 * 144 + 32 * s + 4 * tig);
            qa[s][2] = *(const uint32_t*)(Qb + m1 * 144 + 32 * s + 16 + 4 * tig);
            qa[s][3] = *(const uint32_t*)(Qb + m2 * 144 + 32 * s + 16 + 4 * tig);
        }
    }

    float o[8][4];
    #pragma unroll
    for (int ni = 0; ni < 8; ni++)
        #pragma unroll
        for (int c = 0; c < 4; c++) o[ni][c] = 0.f;
    float m0 = -1e30f, m1v = -1e30f, l0 = 0.f, l1 = 0.f;

    const int r0g = q0 + w * 16 + grp;
    const int r1g = r0g + 8;

    const int nkt = 2 * qt + 2;
    for (int kt = 0; kt < nkt; kt++) {
        const int k0 = kt * 64;
        const int buf = kt & 1;

        // prefetch next tile into the other buffer (overlaps with compute)
        if (kt + 1 < nkt) {
            const int nb = buf ^ 1;
            const int nk0 = k0 + 64;
            #pragma unroll
            for (int t = 0; t < 2; t++) {
                cp16(kdst[nb][t], ksrc[t] + (size_t)nk0 * LDQKV);
                cp16(vdst[nb][t], vsrc[t] + nk0);
            }
            cp_commit();
        }

        const char* Kb = Kbuf[buf];
        const char* Vb = Vbuf[buf];

        // S = Q K^T
        float s[8][4];
        #pragma unroll
        for (int ni = 0; ni < 8; ni++)
            #pragma unroll
            for (int c = 0; c < 4; c++) s[ni][c] = 0.f;
        #pragma unroll
        for (int ks = 0; ks < 4; ks++) {
            #pragma unroll
            for (int ni = 0; ni < 8; ni++) {
                int n = 8 * ni + grp;
                uint32_t bfr[2];
                bfr[0] = *(const uint32_t*)(Kb + n * 144 + 32 * ks + 4 * tig);
                bfr[1] = *(const uint32_t*)(Kb + n * 144 + 32 * ks + 16 + 4 * tig);
                mma_f16(s[ni], qa[ks], bfr);
            }
        }
        #pragma unroll
        for (int ni = 0; ni < 8; ni++)
            #pragma unroll
            for (int c = 0; c < 4; c++) s[ni][c] *= 0.125f;

        if (k0 + 63 > r0g) {
            #pragma unroll
            for (int ni = 0; ni < 8; ni++) {
                int c0 = k0 + ni * 8 + 2 * tig;
                if (c0     > r0g) s[ni][0] = -1e30f;
                if (c0 + 1 > r0g) s[ni][1] = -1e30f;
                if (c0     > r1g) s[ni][2] = -1e30f;
                if (c0 + 1 > r1g) s[ni][3] = -1e30f;
            }
        }

        float pm0 = -1e30f, pm1 = -1e30f;
        #pragma unroll
        for (int ni = 0; ni < 8; ni++) {
            pm0 = fmaxf(pm0, fmaxf(s[ni][0], s[ni][1]));
            pm1 = fmaxf(pm1, fmaxf(s[ni][2], s[ni][3]));
        }
        pm0 = fmaxf(pm0, __shfl_xor_sync(0xffffffffu, pm0, 1));
        pm0 = fmaxf(pm0, __shfl_xor_sync(0xffffffffu, pm0, 2));
        pm1 = fmaxf(pm1, __shfl_xor_sync(0xffffffffu, pm1, 1));
        pm1 = fmaxf(pm1, __shfl_xor_sync(0xffffffffu, pm1, 2));
        float mn0 = fmaxf(m0, pm0), mn1 = fmaxf(m1v, pm1);
        float a0 = __expf(m0 - mn0), a1 = __expf(m1v - mn1);
        m0 = mn0; m1v = mn1;

        float rs0 = 0.f, rs1 = 0.f;
        {
            char* p0p = Pb + (w * 16 + grp) * 144 + 4 * tig;
            char* p1p = p0p + 8 * 144;
            #pragma unroll
            for (int ni = 0; ni < 8; ni++) {
                float e0 = __expf(s[ni][0] - mn0);
                float e1 = __expf(s[ni][1] - mn0);
                float e2 = __expf(s[ni][2] - mn1);
                float e3 = __expf(s[ni][3] - mn1);
                rs0 += e0 + e1; rs1 += e2 + e3;
                *(__half2*)(p0p + ni * 16) = __floats2half2_rn(e0, e1);
                *(__half2*)(p1p + ni * 16) = __floats2half2_rn(e2, e3);
            }
        }
        rs0 += __shfl_xor_sync(0xffffffffu, rs0, 1);
        rs0 += __shfl_xor_sync(0xffffffffu, rs0, 2);
        rs1 += __shfl_xor_sync(0xffffffffu, rs1, 1);
        rs1 += __shfl_xor_sync(0xffffffffu, rs1, 2);
        l0 = l0 * a0 + rs0;
        l1 = l1 * a1 + rs1;

        #pragma unroll
        for (int ni = 0; ni < 8; ni++) {
            o[ni][0] *= a0; o[ni][1] *= a0;
            o[ni][2] *= a1; o[ni][3] *= a1;
        }
        __syncwarp();

        // O += P @ V  (B-frag from Vt rows: key-contiguous)
        {
            int m1r = w * 16 + grp, m2r = m1r + 8;
            #pragma unroll
            for (int ks = 0; ks < 4; ks++) {
                uint32_t pa[4];
                pa[0] = *(const uint32_t*)(Pb + m1r * 144 + 32 * ks + 4 * tig);
                pa[1] = *(const uint32_t*)(Pb + m2r * 144 + 32 * ks + 4 * tig);
                pa[2] = *(const uint32_t*)(Pb + m1r * 144 + 32 * ks + 16 + 4 * tig);
                pa[3] = *(const uint32_t*)(Pb + m2r * 144 + 32 * ks + 16 + 4 * tig);
                #pragma unroll
                for (int ni = 0; ni < 8; ni++) {
                    int d = 8 * ni + grp;
                    uint32_t bfr[2];
                    bfr[0] = *(const uint32_t*)(Vb + d * 144 + 32 * ks + 4 * tig);
                    bfr[1] = *(const uint32_t*)(Vb + d * 144 + 32 * ks + 16 + 4 * tig);
                    mma_f16(o[ni], pa, bfr);
                }
            }
        }

        // wait for prefetched tile kt+1, release both buffers
        if (kt + 1 < nkt) {
            cp_wait0();
            __syncthreads();
        }
    }

    float inv0 = 1.f / l0, inv1 = 1.f / l1;
    #pragma unroll
    for (int ni = 0; ni < 8; ni++) {
        int col = h * HD + ni * 8 + 2 * tig;
        *(__half2*)&att[(rowbase + r0g) * EMB + col] =
            __floats2half2_rn(o[ni][0] * inv0, o[ni][1] * inv0);
        *(__half2*)&att[(rowbase + r1g) * EMB + col] =
            __floats2half2_rn(o[ni][2] * inv1, o[ni][3] * inv1);
    }
}

// ---------------------------------------------------------------------------
extern "C" void kernel_launch(void* const* d_in, const int* in_sizes, int n_in,
                              void* d_out, int out_size)
{
    const float* x      = (const float*)d_in[0];
    const float* w_attn = (const float*)d_in[1];
    const float* b_attn = (const float*)d_in[2];
    const float* w_proj = (const float*)d_in[3];
    const float* b_proj = (const float*)d_in[4];
    float* out = (float*)d_out;

    void *qkvp, *attp, *xhp, *watp, *wptp, *vtp;
    cudaGetSymbolAddress(&qkvp, g_qkv_raw);
    cudaGetSymbolAddress(&attp, g_att_raw);
    cudaGetSymbolAddress(&xhp,  g_xh_raw);
    cudaGetSymbolAddress(&watp, g_wat_raw);
    cudaGetSymbolAddress(&wptp, g_wpt_raw);
    cudaGetSymbolAddress(&vtp,  g_vt_raw);
    __half* qkv = (__half*)qkvp;
    __half* att = (__half*)attp;
    __half* xh  = (__half*)xhp;
    __half* wat = (__half*)watp;
    __half* wpt = (__half*)wptp;
    __half* vtr = (__half*)vtp;

    cudaFuncSetAttribute(gemm_f16, cudaFuncAttributeMaxDynamicSharedMemorySize, GEMM_SMEM_BYTES);
    cudaFuncSetAttribute(attn_f16, cudaFuncAttributeMaxDynamicSharedMemorySize, ATTN_SMEM_BYTES);

    // 0) prepass: x -> half; weights -> half + transpose ([N][K])
    to_half_kernel<<<(MROWS * EMB / 2 + 255) / 256, 256>>>(x, xh, MROWS * EMB / 2);
    {
        dim3 blk(32, 8);
        dim3 g1(LDQKV / 32, EMB / 32);
        transpose_half_kernel<<<g1, blk>>>(w_attn, wat, EMB, LDQKV);
        dim3 g2(EMB / 32, EMB / 32);
        transpose_half_kernel<<<g2, blk>>>(w_proj, wpt, EMB, EMB);
    }

    // 1) qkv(half) = x @ w_attn + b_attn
    {
        dim3 grid(LDQKV / BN, MROWS / BM);
        gemm_f16<<<grid, GT, GEMM_SMEM_BYTES>>>(xh, wat, b_attn, qkv, LDQKV, EMB, 1);
    }
    // 1b) transpose V slice of qkv -> vt
    {
        dim3 grid(SEQ / 64, NH, BATCH);
        transpose_v_kernel<<<grid, 256>>>(qkv, vtr);
    }
    // 2) fp16 flash attention -> att(half)
    {
        dim3 grid(SEQ / 128, NH, BATCH);
        attn_f16<<<grid, 256, ATTN_SMEM_BYTES>>>(qkv, vtr, att);
    }
    // 3) out(fp32) = att @ w_proj + b_proj
    {
        dim3 grid(EMB / BN, MROWS / BM);
        gemm_f16<<<grid, GT, GEMM_SMEM_BYTES>>>(att, wpt, b_proj, out, EMB, EMB, 0);
    }
}